// round 2
// baseline (speedup 1.0000x reference)
#include <cuda_runtime.h>
#include <cuda_bf16.h>
#include <float.h>

#define BATCH 256
#define NQ 1000
#define NC 80
#define TOPK 300
#define THRESH 0.05f
#define SORT_N 1024

typedef unsigned long long u64;
typedef unsigned int u32;

// Scratch (no allocations allowed in kernel_launch)
__device__ u64   g_keys[BATCH * NQ];
__device__ float g_scores[BATCH * NQ];
__device__ int   g_labels[BATCH * NQ];

// Order-preserving bijection float -> uint32 (monotone increasing)
__device__ __forceinline__ u32 fkey(float f) {
    u32 u = __float_as_uint(f);
    return (u & 0x80000000u) ? ~u : (u | 0x80000000u);
}
__device__ __forceinline__ float ikey(u32 k) {
    u32 u = (k & 0x80000000u) ? (k ^ 0x80000000u) : ~k;
    return __uint_as_float(u);
}

// Kernel 1: one warp per TWO queries (MLP=2). Per query: lane-local max over 4
// classes, then REDUX.UMAX on monotone key bits + ballot (lowest lane = lowest
// class -> exact jax argmax tie-break) + broadcast shfl for the class.
__global__ void __launch_bounds__(256) k_maxarg(const float* __restrict__ logits) {
    int gw   = (blockIdx.x * 256 + threadIdx.x) >> 5;
    int lane = threadIdx.x & 31;
    if (gw >= BATCH * NQ / 2) return;
    int q0 = gw * 2;

    const float4* base = reinterpret_cast<const float4*>(logits);
    float v0 = -FLT_MAX, v1 = -FLT_MAX;
    int   c0 = 127,      c1 = 127;
    if (lane < NC / 4) {
        float4 a = base[(size_t)q0 * 20 + lane];
        float4 b = base[(size_t)q0 * 20 + 20 + lane];
        v0 = a.x; c0 = 4 * lane;
        if (a.y > v0) { v0 = a.y; c0 = 4 * lane + 1; }
        if (a.z > v0) { v0 = a.z; c0 = 4 * lane + 2; }
        if (a.w > v0) { v0 = a.w; c0 = 4 * lane + 3; }
        v1 = b.x; c1 = 4 * lane;
        if (b.y > v1) { v1 = b.y; c1 = 4 * lane + 1; }
        if (b.z > v1) { v1 = b.z; c1 = 4 * lane + 2; }
        if (b.w > v1) { v1 = b.w; c1 = 4 * lane + 3; }
    }
    u32 fk0 = fkey(v0), fk1 = fkey(v1);
    u32 m0 = __reduce_max_sync(0xffffffffu, fk0);
    u32 m1 = __reduce_max_sync(0xffffffffu, fk1);
    u32 ms0 = __ballot_sync(0xffffffffu, fk0 == m0);
    u32 ms1 = __ballot_sync(0xffffffffu, fk1 == m1);
    int cc0 = __shfl_sync(0xffffffffu, c0, __ffs(ms0) - 1);
    int cc1 = __shfl_sync(0xffffffffu, c1, __ffs(ms1) - 1);

    if (lane < 2) {
        int   q = q0 + lane;
        float v = lane ? ikey(m1) : ikey(m0);
        int   c = lane ? cc1 : cc0;
        float s = 1.0f / (1.0f + expf(-v));
        float masked = (s > THRESH) ? s : -1.0f;
        g_scores[q] = s;
        g_labels[q] = c;
        g_keys[q] = ((u64)fkey(masked) << 10) | (u64)(1023 - q % NQ);
    }
}

// Kernel 2: 2 batches per 1024-thread block (128 blocks = 1 wave).
// Warp-synchronous bitonic sort: strides j<=32 stay within each warp's
// 64-element chunk -> __syncwarp; only j>=64 (and the phase right after)
// need __syncthreads. Branchless compare-exchange.
__global__ void __launch_bounds__(1024) k_topk(const float* __restrict__ boxes,
                                               const float* __restrict__ tsizes,
                                               float* __restrict__ out) {
    __shared__ u64 sk[2][SORT_N];
    int t   = threadIdx.x;
    int sub = t >> 9;
    int tt  = t & 511;
    int b   = blockIdx.x * 2 + sub;
    u64* s  = sk[sub];

    for (int i = tt; i < SORT_N; i += 512)
        s[i] = (i < NQ) ? g_keys[b * NQ + i] : 0ULL;   // pad sorts below all real keys
    __syncthreads();

    int jp = 64;  // force nothing; first phase sync already done above
    bool first = true;
    for (int k = 2; k <= SORT_N; k <<= 1) {
        #pragma unroll 1
        for (int j = k >> 1; j > 0; j >>= 1) {
            if (!first) {
                if (j >= 64 || jp >= 64) __syncthreads();
                else                     __syncwarp();
            }
            first = false;
            int i = ((tt & ~(j - 1)) << 1) | (tt & (j - 1));
            int p = i + j;
            u64 a = s[i], c2 = s[p];
            bool desc = (i & k) == 0;
            bool sw = desc ? (a < c2) : (a > c2);
            s[i] = sw ? c2 : a;
            s[p] = sw ? a : c2;
            jp = j;
        }
    }
    __syncthreads();

    float img_h = tsizes[b * 2 + 0];
    float img_w = tsizes[b * 2 + 1];

    if (tt < TOPK) {
        u64 key = s[tt];
        int qi = 1023 - (int)(key & 1023ULL);
        int o = b * TOPK + tt;
        float* ob = out + 2 * BATCH * TOPK + (size_t)o * 4;

        float sc = g_scores[b * NQ + qi];
        bool valid = sc > THRESH;
        float4 bx = reinterpret_cast<const float4*>(boxes)[b * NQ + qi];
        float x0 = (bx.x - 0.5f * bx.z) * img_w;
        float y0 = (bx.y - 0.5f * bx.w) * img_h;
        float x1 = (bx.x + 0.5f * bx.z) * img_w;
        float y1 = (bx.y + 0.5f * bx.w) * img_h;

        out[o] = valid ? sc : 0.0f;
        out[BATCH * TOPK + o] = valid ? (float)g_labels[b * NQ + qi] : -1.0f;
        ob[0] = valid ? x0 : 0.0f;
        ob[1] = valid ? y0 : 0.0f;
        ob[2] = valid ? x1 : 0.0f;
        ob[3] = valid ? y1 : 0.0f;
    }
}

extern "C" void kernel_launch(void* const* d_in, const int* in_sizes, int n_in,
                              void* d_out, int out_size) {
    const float* pred_logits  = (const float*)d_in[0];
    const float* pred_boxes   = (const float*)d_in[1];
    const float* target_sizes = (const float*)d_in[2];
    float* out = (float*)d_out;

    int warps1  = BATCH * NQ / 2;                 // 128000 warps, 2 queries each
    int blocks1 = (warps1 * 32 + 255) / 256;
    k_maxarg<<<blocks1, 256>>>(pred_logits);

    k_topk<<<BATCH / 2, 1024>>>(pred_boxes, target_sizes, out);
}